// round 11
// baseline (speedup 1.0000x reference)
#include <cuda_runtime.h>
#include <cuda_bf16.h>
#include <math.h>
#include <stdint.h>

#define BATCH   1024
#define NTOK    64
#define DIM     512
#define HEADS   16
#define HDIM    32
#define NW      64
#define ROWS    (BATCH * NTOK)      // 65536
#define QKVCOLS (3 * DIM)           // 1536

// ---------------- device scratch ----------------
__device__ __align__(16) float         g_qkv[(size_t)ROWS * QKVCOLS];
__device__ __align__(16) __nv_bfloat16 g_xh[(size_t)ROWS * DIM];
__device__ __align__(16) __nv_bfloat16 g_xl[(size_t)ROWS * DIM];
__device__ __align__(16) __nv_bfloat16 g_wh[(size_t)QKVCOLS * DIM];
__device__ __align__(16) __nv_bfloat16 g_wl[(size_t)QKVCOLS * DIM];
__device__ __align__(16) __nv_bfloat16 g_ph[(size_t)DIM * DIM];
__device__ __align__(16) __nv_bfloat16 g_pl[(size_t)DIM * DIM];
__device__ __align__(16) __nv_bfloat16 g_aoh[(size_t)ROWS * DIM];
__device__ __align__(16) __nv_bfloat16 g_aol[(size_t)ROWS * DIM];
__device__ float g_bias_table[225 * HEADS];
__device__ float g_rel_bias[HEADS * NTOK * NTOK];
__device__ float g_scale[HEADS];

// ---------------- helpers ----------------
__device__ __forceinline__ uint32_t smem_u32(const void* p) {
    uint32_t a;
    asm("{ .reg .u64 t; cvta.to.shared.u64 t, %1; cvt.u32.u64 %0, t; }" : "=r"(a) : "l"(p));
    return a;
}

#define LDSM4(r0,r1,r2,r3, addr) \
    asm volatile("ldmatrix.sync.aligned.m8n8.x4.shared.b16 {%0,%1,%2,%3}, [%4];" \
        : "=r"(r0),"=r"(r1),"=r"(r2),"=r"(r3) : "r"(addr))

#define MMA_BF16(d, a, b) \
    asm volatile("mma.sync.aligned.m16n8k16.row.col.f32.bf16.bf16.f32 " \
        "{%0,%1,%2,%3}, {%4,%5,%6,%7}, {%8,%9}, {%0,%1,%2,%3};" \
        : "+f"(d[0]),"+f"(d[1]),"+f"(d[2]),"+f"(d[3]) \
        : "r"(a[0]),"r"(a[1]),"r"(a[2]),"r"(a[3]),"r"(b[0]),"r"(b[1]))

#define CP16(dst, src) \
    asm volatile("cp.async.ca.shared.global [%0], [%1], 16;" :: "r"(dst), "l"(src))
#define CP_COMMIT() asm volatile("cp.async.commit_group;" ::: "memory")
#define CP_WAIT1()  asm volatile("cp.async.wait_group 1;" ::: "memory")

// ---- packed f32x2 (FFMA2) ----
typedef unsigned long long u64t;
__device__ __forceinline__ u64t pk2(float lo, float hi) {
    u64t r; asm("mov.b64 %0, {%1, %2};" : "=l"(r) : "f"(lo), "f"(hi)); return r;
}
__device__ __forceinline__ void fma2(u64t& d, u64t a, u64t b) {
    asm("fma.rn.f32x2 %0, %1, %2, %0;" : "+l"(d) : "l"(a), "l"(b));
}
__device__ __forceinline__ float2 upk2(u64t v) {
    float2 r; asm("mov.b64 {%0, %1}, %2;" : "=f"(r.x), "=f"(r.y) : "l"(v)); return r;
}

// ---------------- fp32 -> bf16 hi/lo split ----------------
__global__ void split_f32(const float* __restrict__ in,
                          __nv_bfloat16* __restrict__ hi,
                          __nv_bfloat16* __restrict__ lo, int n4)
{
    int i = blockIdx.x * blockDim.x + threadIdx.x;
    if (i >= n4) return;
    float4 v = ((const float4*)in)[i];
    __nv_bfloat16 h[4], l[4];
    float x[4] = {v.x, v.y, v.z, v.w};
    #pragma unroll
    for (int j = 0; j < 4; j++) {
        h[j] = __float2bfloat16(x[j]);
        l[j] = __float2bfloat16(x[j] - __bfloat162float(h[j]));
    }
    ((uint2*)hi)[i] = *(uint2*)h;
    ((uint2*)lo)[i] = *(uint2*)l;
}

// ---------------- CPB MLP ----------------
__global__ void cpb_mlp_kernel(const float* __restrict__ tbl,
                               const float* __restrict__ w1,
                               const float* __restrict__ b1,
                               const float* __restrict__ w2)
{
    int i = blockIdx.x, j = threadIdx.x;
    __shared__ float hid[512];
    float hv = tbl[i*2+0] * w1[j*2+0] + tbl[i*2+1] * w1[j*2+1] + b1[j];
    hid[j] = fmaxf(hv, 0.0f);
    __syncthreads();
    int warp = j >> 5, lane = j & 31;
    float s = 0.0f;
    #pragma unroll
    for (int c = lane; c < 512; c += 32) s += hid[c] * w2[warp*512 + c];
    #pragma unroll
    for (int off = 16; off > 0; off >>= 1) s += __shfl_xor_sync(0xffffffffu, s, off);
    if (lane == 0) g_bias_table[i*HEADS + warp] = s;
}

__global__ void cpb_expand_kernel(const int* __restrict__ idx,
                                  const float* __restrict__ logit_scale)
{
    int g = blockIdx.x * 256 + threadIdx.x;
    int h = g >> 12, nm = g & 4095;
    float v = g_bias_table[idx[nm]*HEADS + h];
    g_rel_bias[g] = 16.0f / (1.0f + expf(-v));
    if (g < HEADS) g_scale[g] = expf(fminf(logit_scale[g], 4.60517018598809136804f));
}

// ---------------------------------------------------------------------------
// split-bf16 GEMM (NT): C[M,N] = (Ah+Al)[M,K] @ (Bh+Bl)[N,K]^T + bias
// BM=128 BN=128 BK=32, K=512. 512 thr = 16 warps (4m x 4n), warp 32x32.
// 3-stage cp.async pipeline. smem rows padded to 80B (conflict-free LDSM).
// ---------------------------------------------------------------------------
#define AB_SZ 10240
#define STG (4 * AB_SZ)          // 40960
#define GEMM_SMEM (3 * STG)      // 122880

template <int MODE>   // 0: qkv bias (q|0|v), 1: proj bias
__global__ __launch_bounds__(512, 1) void gemm_bf16_128(
    const __nv_bfloat16* __restrict__ Ah, const __nv_bfloat16* __restrict__ Al,
    const __nv_bfloat16* __restrict__ Bh, const __nv_bfloat16* __restrict__ Bl,
    const float* __restrict__ bias0, const float* __restrict__ bias1,
    float* __restrict__ C, int N)
{
    extern __shared__ char smem[];

    const int tid  = threadIdx.x;
    const int bm   = blockIdx.y * 128;
    const int bn   = blockIdx.x * 128;
    const int wid  = tid >> 5, lane = tid & 31;
    const int wm   = (wid & 3) * 32;
    const int wn   = (wid >> 2) * 32;

    const uint32_t sbase = smem_u32(smem);

    float acc[2][4][4];
    #pragma unroll
    for (int a = 0; a < 2; a++)
        #pragma unroll
        for (int b = 0; b < 4; b++)
            #pragma unroll
            for (int c = 0; c < 4; c++) acc[a][b][c] = 0.0f;

    const int lrow = tid >> 2;       // 0..127
    const int lq   = tid & 3;        // 0..3
    auto load_stage = [&](int kt, int buf) {
        const uint32_t sb = sbase + buf * STG;
        const size_t goff_a = (size_t)(bm + lrow) * 512 + kt * 32 + lq * 8;
        const size_t goff_b = (size_t)(bn + lrow) * 512 + kt * 32 + lq * 8;
        const uint32_t d = sb + (uint32_t)(lrow * 80 + lq * 16);
        CP16(d,             (const char*)Ah + goff_a * 2);
        CP16(d +   AB_SZ,   (const char*)Al + goff_a * 2);
        CP16(d + 2*AB_SZ,   (const char*)Bh + goff_b * 2);
        CP16(d + 3*AB_SZ,   (const char*)Bl + goff_b * 2);
        CP_COMMIT();
    };

    load_stage(0, 0);
    load_stage(1, 1);

    for (int kt = 0; kt < 16; kt++) {
        const int buf = kt % 3;
        CP_WAIT1();
        __syncthreads();

        if (kt + 2 < 16) load_stage(kt + 2, (kt + 2) % 3);
        else CP_COMMIT();

        const uint32_t sb  = sbase + buf * STG;
        const uint32_t aAh = sb;
        const uint32_t aAl = sb +   AB_SZ;
        const uint32_t aBh = sb + 2*AB_SZ;
        const uint32_t aBl = sb + 3*AB_SZ;

        #pragma unroll
        for (int ks = 0; ks < 2; ks++) {
            const int kb = ks * 16;
            uint32_t ah[2][4], al[2][4], bh[4][2], bl[4][2];
            #pragma unroll
            for (int mt = 0; mt < 2; mt++) {
                int row = wm + mt*16 + (lane & 15);
                int col = kb + (lane >> 4) * 8;
                uint32_t off = (uint32_t)(row*80 + col*2);
                LDSM4(ah[mt][0], ah[mt][1], ah[mt][2], ah[mt][3], aAh + off);
                LDSM4(al[mt][0], al[mt][1], al[mt][2], al[mt][3], aAl + off);
            }
            #pragma unroll
            for (int np = 0; np < 2; np++) {
                int g = lane >> 3;
                int row = wn + np*16 + (lane & 7) + ((g >> 1) & 1) * 8;
                int col = kb + (g & 1) * 8;
                uint32_t off = (uint32_t)(row*80 + col*2);
                LDSM4(bh[2*np][0], bh[2*np][1], bh[2*np+1][0], bh[2*np+1][1], aBh + off);
                LDSM4(bl[2*np][0], bl[2*np][1], bl[2*np+1][0], bl[2*np+1][1], aBl + off);
            }
            #pragma unroll
            for (int mt = 0; mt < 2; mt++)
                #pragma unroll
                for (int nt = 0; nt < 4; nt++) {
                    MMA_BF16(acc[mt][nt], ah[mt], bh[nt]);
                    MMA_BF16(acc[mt][nt], ah[mt], bl[nt]);
                    MMA_BF16(acc[mt][nt], al[mt], bh[nt]);
                }
        }
        __syncthreads();
    }

    #pragma unroll
    for (int mt = 0; mt < 2; mt++) {
        #pragma unroll
        for (int nt = 0; nt < 4; nt++) {
            int row = bm + wm + mt*16 + (lane >> 2);
            int col = bn + wn + nt*8 + (lane & 3)*2;
            float b0, b1;
            if (MODE == 0) {
                b0 = (col   < 512) ? bias0[col]   : ((col   < 1024) ? 0.0f : bias1[col - 1024]);
                b1 = (col+1 < 512) ? bias0[col+1] : ((col+1 < 1024) ? 0.0f : bias1[col+1 - 1024]);
            } else {
                b0 = bias0[col]; b1 = bias0[col+1];
            }
            float* p0 = C + (size_t)row * N + col;
            float* p1 = C + (size_t)(row + 8) * N + col;
            p0[0] = acc[mt][nt][0] + b0;  p0[1] = acc[mt][nt][1] + b1;
            p1[0] = acc[mt][nt][2] + b0;  p1[1] = acc[mt][nt][3] + b1;
        }
    }
}

// ---------------------------------------------------------------------------
// Fused window attention per (b,h). Pt aliased over dead qs/ks storage:
// smem 44.5 -> 27.1 KB, 8 blocks/SM. f32x2 FMA in S and PV, register softmax,
// swizzled Pt. Writes attn output as bf16 hi/lo for the 3-term proj GEMM.
// ---------------------------------------------------------------------------
__global__ __launch_bounds__(256) void attn_kernel(const float* __restrict__ qkv,
                                                   const float* __restrict__ mask,
                                                   __nv_bfloat16* __restrict__ aoh,
                                                   __nv_bfloat16* __restrict__ aol)
{
    const int b = blockIdx.x;
    const int h = blockIdx.y;
    const int w = b & (NW - 1);
    const int tid = threadIdx.x;
    const int wid = tid >> 5, lane = tid & 31;

    // pool: qs[64][36] @ 0, ks[64][36] @ 2304 ; Pt[64][68] aliased @ 0 (4352 fl)
    __shared__ __align__(16) float pool[4608];
    __shared__ __align__(16) float vs[64][32];
    __shared__ float qn[64], kn[64];
    #define QS(n, d) pool[(n)*36 + (d)]
    #define KS(n, d) pool[2304 + (n)*36 + (d)]
    #define PT(m, c) pool[(m)*68 + (c)]

    const float* base = qkv + (size_t)b * NTOK * QKVCOLS + h * HDIM;
    #pragma unroll
    for (int i = 0; i < 8; i++) {
        int n = wid + i * 8;
        const float* r = base + (size_t)n * QKVCOLS;
        QS(n, lane) = r[lane];
        KS(n, lane) = r[512 + lane];
        vs[n][lane] = r[1024 + lane];
    }
    __syncthreads();

    // inverse norms (reads qs/ks; completes before the post-S barrier)
    if (tid < 128) {
        int n = tid & 63;
        bool isq = tid < 64;
        const float4* rr = (const float4*)(isq ? &QS(n, 0) : &KS(n, 0));
        float s = 0.0f;
        #pragma unroll
        for (int j = 0; j < 8; j++) {
            float4 v = rr[j];
            s = fmaf(v.x, v.x, s); s = fmaf(v.y, v.y, s);
            s = fmaf(v.z, v.z, s); s = fmaf(v.w, v.w, s);
        }
        float inv = 1.0f / fmaxf(sqrtf(s), 1e-12f);
        if (isq) qn[n] = inv; else kn[n] = inv;
    }

    // S: warp wid owns rows n = wid*8..+7; lane owns cols (lane, lane+32)
    u64t s01[8];
    #pragma unroll
    for (int r = 0; r < 8; r++) s01[r] = pk2(0.0f, 0.0f);
    #pragma unroll
    for (int d4 = 0; d4 < 32; d4 += 4) {
        float4 kv0 = *(const float4*)&KS(lane, d4);
        float4 kv1 = *(const float4*)&KS(lane + 32, d4);
        u64t kx = pk2(kv0.x, kv1.x);
        u64t ky = pk2(kv0.y, kv1.y);
        u64t kz = pk2(kv0.z, kv1.z);
        u64t kw = pk2(kv0.w, kv1.w);
        #pragma unroll
        for (int r = 0; r < 8; r++) {
            float4 qv = *(const float4*)&QS(wid*8 + r, d4);   // broadcast
            fma2(s01[r], pk2(qv.x, qv.x), kx);
            fma2(s01[r], pk2(qv.y, qv.y), ky);
            fma2(s01[r], pk2(qv.z, qv.z), kz);
            fma2(s01[r], pk2(qv.w, qv.w), kw);
        }
    }
    __syncthreads();   // all qs/ks reads done -> Pt may overwrite pool

    const float scale = g_scale[h];
    const float kn0 = kn[lane], kn1 = kn[lane + 32];
    const float* rb = g_rel_bias + h * (NTOK * NTOK);
    const float* mk = mask + (size_t)w * (NTOK * NTOK);

    const int swz0 = (lane & 7) << 3;
    const int swz1 = ((lane + 32) & 7) << 3;
    #pragma unroll
    for (int r = 0; r < 8; r++) {
        int n = wid*8 + r;
        float qsc = qn[n] * scale;
        int off = n*64 + lane;
        float2 sv = upk2(s01[r]);
        float x0 = sv.x*qsc*kn0 + rb[off]      + mk[off];
        float x1 = sv.y*qsc*kn1 + rb[off + 32] + mk[off + 32];
        float mx = fmaxf(x0, x1);
        #pragma unroll
        for (int o = 16; o > 0; o >>= 1)
            mx = fmaxf(mx, __shfl_xor_sync(0xffffffffu, mx, o));
        float e0 = __expf(x0 - mx);
        float e1 = __expf(x1 - mx);
        float sm = e0 + e1;
        #pragma unroll
        for (int o = 16; o > 0; o >>= 1)
            sm += __shfl_xor_sync(0xffffffffu, sm, o);
        float inv = 1.0f / sm;
        PT(lane,      n ^ swz0) = e0 * inv;
        PT(lane + 32, n ^ swz1) = e1 * inv;
    }
    __syncthreads();

    // PV: warp wid rows n = wid*8..+7; lane owns col d = lane
    u64t o01 = pk2(0.f,0.f), o23 = pk2(0.f,0.f), o45 = pk2(0.f,0.f), o67 = pk2(0.f,0.f);
    #pragma unroll
    for (int m = 0; m < 64; m++) {
        float vm = vs[m][lane];
        u64t vmd = pk2(vm, vm);
        const float* prow = &PT(m, (wid ^ (m & 7)) * 8);
        float4 p0 = *(const float4*)(prow);
        float4 p1 = *(const float4*)(prow + 4);
        fma2(o01, pk2(p0.x, p0.y), vmd);
        fma2(o23, pk2(p0.z, p0.w), vmd);
        fma2(o45, pk2(p1.x, p1.y), vmd);
        fma2(o67, pk2(p1.z, p1.w), vmd);
    }
    float o[8];
    { float2 t = upk2(o01); o[0] = t.x; o[1] = t.y; }
    { float2 t = upk2(o23); o[2] = t.x; o[3] = t.y; }
    { float2 t = upk2(o45); o[4] = t.x; o[5] = t.y; }
    { float2 t = upk2(o67); o[6] = t.x; o[7] = t.y; }

    #pragma unroll
    for (int r = 0; r < 8; r++) {
        size_t oi = (size_t)(b*NTOK + wid*8 + r) * DIM + h*HDIM + lane;
        __nv_bfloat16 hi = __float2bfloat16(o[r]);
        __nv_bfloat16 lo = __float2bfloat16(o[r] - __bfloat162float(hi));
        aoh[oi] = hi;
        aol[oi] = lo;
    }
    #undef QS
    #undef KS
    #undef PT
}

// ---------------------------------------------------------------------------
extern "C" void kernel_launch(void* const* d_in, const int* in_sizes, int n_in,
                              void* d_out, int out_size)
{
    const float* x           = (const float*)d_in[0];
    const float* mask        = (const float*)d_in[1];
    const float* qkv_w       = (const float*)d_in[2];
    const float* q_bias      = (const float*)d_in[3];
    const float* v_bias      = (const float*)d_in[4];
    const float* logit_scale = (const float*)d_in[5];
    const float* cpb_w1      = (const float*)d_in[6];
    const float* cpb_b1      = (const float*)d_in[7];
    const float* cpb_w2      = (const float*)d_in[8];
    const float* proj_w      = (const float*)d_in[9];
    const float* proj_b      = (const float*)d_in[10];
    const float* rel_table   = (const float*)d_in[11];
    const int*   rel_idx     = (const int*)d_in[12];
    float*       out         = (float*)d_out;

    float *qkv_ptr;
    __nv_bfloat16 *xh, *xl, *wh, *wl, *ph, *pl, *aoh, *aol;
    cudaGetSymbolAddress((void**)&qkv_ptr, g_qkv);
    cudaGetSymbolAddress((void**)&xh, g_xh);   cudaGetSymbolAddress((void**)&xl, g_xl);
    cudaGetSymbolAddress((void**)&wh, g_wh);   cudaGetSymbolAddress((void**)&wl, g_wl);
    cudaGetSymbolAddress((void**)&ph, g_ph);   cudaGetSymbolAddress((void**)&pl, g_pl);
    cudaGetSymbolAddress((void**)&aoh, g_aoh); cudaGetSymbolAddress((void**)&aol, g_aol);

    cudaFuncSetAttribute(gemm_bf16_128<0>, cudaFuncAttributeMaxDynamicSharedMemorySize, GEMM_SMEM);
    cudaFuncSetAttribute(gemm_bf16_128<1>, cudaFuncAttributeMaxDynamicSharedMemorySize, GEMM_SMEM);

    // splits
    {
        int n4 = ROWS * DIM / 4;
        split_f32<<<(n4 + 255)/256, 256>>>(x, xh, xl, n4);
        n4 = QKVCOLS * DIM / 4;
        split_f32<<<(n4 + 255)/256, 256>>>(qkv_w, wh, wl, n4);
        n4 = DIM * DIM / 4;
        split_f32<<<(n4 + 255)/256, 256>>>(proj_w, ph, pl, n4);
    }

    // CPB
    cpb_mlp_kernel<<<225, 512>>>(rel_table, cpb_w1, cpb_b1, cpb_w2);
    cpb_expand_kernel<<<256, 256>>>(rel_idx, logit_scale);

    // QKV GEMM: [65536,512] x [1536,512]^T -> fp32 [65536,1536]
    gemm_bf16_128<0><<<dim3(QKVCOLS/128, ROWS/128), 512, GEMM_SMEM>>>(
        xh, xl, wh, wl, q_bias, v_bias, qkv_ptr, QKVCOLS);

    // attention (writes bf16 hi/lo)
    attn_kernel<<<dim3(BATCH, HEADS), 256>>>(qkv_ptr, mask, aoh, aol);

    // proj GEMM: [65536,512] x [512,512]^T -> d_out fp32
    gemm_bf16_128<1><<<dim3(DIM/128, ROWS/128), 512, GEMM_SMEM>>>(
        aoh, aol, ph, pl, proj_b, nullptr, out, DIM);
}

// round 12
// speedup vs baseline: 1.0192x; 1.0192x over previous
#include <cuda_runtime.h>
#include <cuda_bf16.h>
#include <math.h>
#include <stdint.h>

#define BATCH   1024
#define NTOK    64
#define DIM     512
#define HEADS   16
#define HDIM    32
#define NW      64
#define ROWS    (BATCH * NTOK)      // 65536
#define QKVCOLS (3 * DIM)           // 1536

// ---------------- device scratch ----------------
__device__ __align__(16) float         g_qkv[(size_t)ROWS * QKVCOLS];
__device__ __align__(16) __nv_bfloat16 g_xh[(size_t)ROWS * DIM];
__device__ __align__(16) __nv_bfloat16 g_xl[(size_t)ROWS * DIM];
__device__ __align__(16) __nv_bfloat16 g_wh[(size_t)QKVCOLS * DIM];
__device__ __align__(16) __nv_bfloat16 g_wl[(size_t)QKVCOLS * DIM];
__device__ __align__(16) __nv_bfloat16 g_ph[(size_t)DIM * DIM];
__device__ __align__(16) __nv_bfloat16 g_pl[(size_t)DIM * DIM];
__device__ __align__(16) __nv_bfloat16 g_aoh[(size_t)ROWS * DIM];
__device__ __align__(16) __nv_bfloat16 g_aol[(size_t)ROWS * DIM];
__device__ float g_bias_table[225 * HEADS];
__device__ float g_rel_bias[HEADS * NTOK * NTOK];
__device__ float g_scale[HEADS];

// ---------------- helpers ----------------
__device__ __forceinline__ uint32_t smem_u32(const void* p) {
    uint32_t a;
    asm("{ .reg .u64 t; cvta.to.shared.u64 t, %1; cvt.u32.u64 %0, t; }" : "=r"(a) : "l"(p));
    return a;
}

#define LDSM4(r0,r1,r2,r3, addr) \
    asm volatile("ldmatrix.sync.aligned.m8n8.x4.shared.b16 {%0,%1,%2,%3}, [%4];" \
        : "=r"(r0),"=r"(r1),"=r"(r2),"=r"(r3) : "r"(addr))

#define MMA_BF16(d, a, b) \
    asm volatile("mma.sync.aligned.m16n8k16.row.col.f32.bf16.bf16.f32 " \
        "{%0,%1,%2,%3}, {%4,%5,%6,%7}, {%8,%9}, {%0,%1,%2,%3};" \
        : "+f"(d[0]),"+f"(d[1]),"+f"(d[2]),"+f"(d[3]) \
        : "r"(a[0]),"r"(a[1]),"r"(a[2]),"r"(a[3]),"r"(b[0]),"r"(b[1]))

#define CP16(dst, src) \
    asm volatile("cp.async.ca.shared.global [%0], [%1], 16;" :: "r"(dst), "l"(src))
#define CP_COMMIT() asm volatile("cp.async.commit_group;" ::: "memory")
#define CP_WAIT1()  asm volatile("cp.async.wait_group 1;" ::: "memory")

// ---- packed f32x2 (FFMA2) ----
typedef unsigned long long u64t;
__device__ __forceinline__ u64t pk2(float lo, float hi) {
    u64t r; asm("mov.b64 %0, {%1, %2};" : "=l"(r) : "f"(lo), "f"(hi)); return r;
}
__device__ __forceinline__ void fma2(u64t& d, u64t a, u64t b) {
    asm("fma.rn.f32x2 %0, %1, %2, %0;" : "+l"(d) : "l"(a), "l"(b));
}
__device__ __forceinline__ float2 upk2(u64t v) {
    float2 r; asm("mov.b64 {%0, %1}, %2;" : "=f"(r.x), "=f"(r.y) : "l"(v)); return r;
}

// ---------------- fp32 -> bf16 hi/lo split ----------------
__global__ void split_f32(const float* __restrict__ in,
                          __nv_bfloat16* __restrict__ hi,
                          __nv_bfloat16* __restrict__ lo, int n4)
{
    int i = blockIdx.x * blockDim.x + threadIdx.x;
    if (i >= n4) return;
    float4 v = ((const float4*)in)[i];
    __nv_bfloat16 h[4], l[4];
    float x[4] = {v.x, v.y, v.z, v.w};
    #pragma unroll
    for (int j = 0; j < 4; j++) {
        h[j] = __float2bfloat16(x[j]);
        l[j] = __float2bfloat16(x[j] - __bfloat162float(h[j]));
    }
    ((uint2*)hi)[i] = *(uint2*)h;
    ((uint2*)lo)[i] = *(uint2*)l;
}

// ---------------- CPB MLP ----------------
__global__ void cpb_mlp_kernel(const float* __restrict__ tbl,
                               const float* __restrict__ w1,
                               const float* __restrict__ b1,
                               const float* __restrict__ w2)
{
    int i = blockIdx.x, j = threadIdx.x;
    __shared__ float hid[512];
    float hv = tbl[i*2+0] * w1[j*2+0] + tbl[i*2+1] * w1[j*2+1] + b1[j];
    hid[j] = fmaxf(hv, 0.0f);
    __syncthreads();
    int warp = j >> 5, lane = j & 31;
    float s = 0.0f;
    #pragma unroll
    for (int c = lane; c < 512; c += 32) s += hid[c] * w2[warp*512 + c];
    #pragma unroll
    for (int off = 16; off > 0; off >>= 1) s += __shfl_xor_sync(0xffffffffu, s, off);
    if (lane == 0) g_bias_table[i*HEADS + warp] = s;
}

__global__ void cpb_expand_kernel(const int* __restrict__ idx,
                                  const float* __restrict__ logit_scale)
{
    int g = blockIdx.x * 256 + threadIdx.x;
    int h = g >> 12, nm = g & 4095;
    float v = g_bias_table[idx[nm]*HEADS + h];
    g_rel_bias[g] = 16.0f / (1.0f + expf(-v));
    if (g < HEADS) g_scale[g] = expf(fminf(logit_scale[g], 4.60517018598809136804f));
}

// ---------------------------------------------------------------------------
// split-bf16 GEMM (NT): C[M,N] = (Ah+Al)[M,K] @ (Bh+Bl)[N,K]^T + bias
// BM=128 BN=128 BK=32, K=512. 512 thr = 16 warps (4m x 4n), warp 32x32.
// 3-stage cp.async pipeline, ONE barrier per k-iter (end-of-iter sync proved
// redundant by the 3-buffer rotation). smem rows padded to 80B.
// ---------------------------------------------------------------------------
#define AB_SZ 10240
#define STG (4 * AB_SZ)          // 40960
#define GEMM_SMEM (3 * STG)      // 122880

template <int MODE>   // 0: qkv bias (q|0|v), 1: proj bias
__global__ __launch_bounds__(512, 1) void gemm_bf16_128(
    const __nv_bfloat16* __restrict__ Ah, const __nv_bfloat16* __restrict__ Al,
    const __nv_bfloat16* __restrict__ Bh, const __nv_bfloat16* __restrict__ Bl,
    const float* __restrict__ bias0, const float* __restrict__ bias1,
    float* __restrict__ C, int N)
{
    extern __shared__ char smem[];

    const int tid  = threadIdx.x;
    const int bm   = blockIdx.y * 128;
    const int bn   = blockIdx.x * 128;
    const int wid  = tid >> 5, lane = tid & 31;
    const int wm   = (wid & 3) * 32;
    const int wn   = (wid >> 2) * 32;

    const uint32_t sbase = smem_u32(smem);

    float acc[2][4][4];
    #pragma unroll
    for (int a = 0; a < 2; a++)
        #pragma unroll
        for (int b = 0; b < 4; b++)
            #pragma unroll
            for (int c = 0; c < 4; c++) acc[a][b][c] = 0.0f;

    const int lrow = tid >> 2;       // 0..127
    const int lq   = tid & 3;        // 0..3
    auto load_stage = [&](int kt, int buf) {
        const uint32_t sb = sbase + buf * STG;
        const size_t goff_a = (size_t)(bm + lrow) * 512 + kt * 32 + lq * 8;
        const size_t goff_b = (size_t)(bn + lrow) * 512 + kt * 32 + lq * 8;
        const uint32_t d = sb + (uint32_t)(lrow * 80 + lq * 16);
        CP16(d,             (const char*)Ah + goff_a * 2);
        CP16(d +   AB_SZ,   (const char*)Al + goff_a * 2);
        CP16(d + 2*AB_SZ,   (const char*)Bh + goff_b * 2);
        CP16(d + 3*AB_SZ,   (const char*)Bl + goff_b * 2);
        CP_COMMIT();
    };

    load_stage(0, 0);
    load_stage(1, 1);

    for (int kt = 0; kt < 16; kt++) {
        const int buf = kt % 3;
        CP_WAIT1();
        __syncthreads();   // single barrier per iter: stage kt visible to all;
                           // also proves compute kt-1 done -> buf (kt-1)%3 free

        if (kt + 2 < 16) load_stage(kt + 2, (kt + 2) % 3);
        else CP_COMMIT();   // keep group accounting uniform

        const uint32_t sb  = sbase + buf * STG;
        const uint32_t aAh = sb;
        const uint32_t aAl = sb +   AB_SZ;
        const uint32_t aBh = sb + 2*AB_SZ;
        const uint32_t aBl = sb + 3*AB_SZ;

        #pragma unroll
        for (int ks = 0; ks < 2; ks++) {
            const int kb = ks * 16;
            uint32_t ah[2][4], al[2][4], bh[4][2], bl[4][2];
            #pragma unroll
            for (int mt = 0; mt < 2; mt++) {
                int row = wm + mt*16 + (lane & 15);
                int col = kb + (lane >> 4) * 8;
                uint32_t off = (uint32_t)(row*80 + col*2);
                LDSM4(ah[mt][0], ah[mt][1], ah[mt][2], ah[mt][3], aAh + off);
                LDSM4(al[mt][0], al[mt][1], al[mt][2], al[mt][3], aAl + off);
            }
            #pragma unroll
            for (int np = 0; np < 2; np++) {
                int g = lane >> 3;
                int row = wn + np*16 + (lane & 7) + ((g >> 1) & 1) * 8;
                int col = kb + (g & 1) * 8;
                uint32_t off = (uint32_t)(row*80 + col*2);
                LDSM4(bh[2*np][0], bh[2*np][1], bh[2*np+1][0], bh[2*np+1][1], aBh + off);
                LDSM4(bl[2*np][0], bl[2*np][1], bl[2*np+1][0], bl[2*np+1][1], aBl + off);
            }
            #pragma unroll
            for (int mt = 0; mt < 2; mt++)
                #pragma unroll
                for (int nt = 0; nt < 4; nt++) {
                    MMA_BF16(acc[mt][nt], ah[mt], bh[nt]);
                    MMA_BF16(acc[mt][nt], ah[mt], bl[nt]);
                    MMA_BF16(acc[mt][nt], al[mt], bh[nt]);
                }
        }
    }

    #pragma unroll
    for (int mt = 0; mt < 2; mt++) {
        #pragma unroll
        for (int nt = 0; nt < 4; nt++) {
            int row = bm + wm + mt*16 + (lane >> 2);
            int col = bn + wn + nt*8 + (lane & 3)*2;
            float b0, b1;
            if (MODE == 0) {
                b0 = (col   < 512) ? bias0[col]   : ((col   < 1024) ? 0.0f : bias1[col - 1024]);
                b1 = (col+1 < 512) ? bias0[col+1] : ((col+1 < 1024) ? 0.0f : bias1[col+1 - 1024]);
            } else {
                b0 = bias0[col]; b1 = bias0[col+1];
            }
            float* p0 = C + (size_t)row * N + col;
            float* p1 = C + (size_t)(row + 8) * N + col;
            p0[0] = acc[mt][nt][0] + b0;  p0[1] = acc[mt][nt][1] + b1;
            p1[0] = acc[mt][nt][2] + b0;  p1[1] = acc[mt][nt][3] + b1;
        }
    }
}

// ---------------------------------------------------------------------------
// Fused window attention per (b,h). Pt aliased over dead qs/ks storage
// (27.1 KB smem), f32x2 FMA, register softmax, swizzled Pt.
// ---------------------------------------------------------------------------
__global__ __launch_bounds__(256) void attn_kernel(const float* __restrict__ qkv,
                                                   const float* __restrict__ mask,
                                                   __nv_bfloat16* __restrict__ aoh,
                                                   __nv_bfloat16* __restrict__ aol)
{
    const int b = blockIdx.x;
    const int h = blockIdx.y;
    const int w = b & (NW - 1);
    const int tid = threadIdx.x;
    const int wid = tid >> 5, lane = tid & 31;

    __shared__ __align__(16) float pool[4608];
    __shared__ __align__(16) float vs[64][32];
    __shared__ float qn[64], kn[64];
    #define QS(n, d) pool[(n)*36 + (d)]
    #define KS(n, d) pool[2304 + (n)*36 + (d)]
    #define PT(m, c) pool[(m)*68 + (c)]

    const float* base = qkv + (size_t)b * NTOK * QKVCOLS + h * HDIM;
    #pragma unroll
    for (int i = 0; i < 8; i++) {
        int n = wid + i * 8;
        const float* r = base + (size_t)n * QKVCOLS;
        QS(n, lane) = r[lane];
        KS(n, lane) = r[512 + lane];
        vs[n][lane] = r[1024 + lane];
    }
    __syncthreads();

    if (tid < 128) {
        int n = tid & 63;
        bool isq = tid < 64;
        const float4* rr = (const float4*)(isq ? &QS(n, 0) : &KS(n, 0));
        float s = 0.0f;
        #pragma unroll
        for (int j = 0; j < 8; j++) {
            float4 v = rr[j];
            s = fmaf(v.x, v.x, s); s = fmaf(v.y, v.y, s);
            s = fmaf(v.z, v.z, s); s = fmaf(v.w, v.w, s);
        }
        float inv = 1.0f / fmaxf(sqrtf(s), 1e-12f);
        if (isq) qn[n] = inv; else kn[n] = inv;
    }

    u64t s01[8];
    #pragma unroll
    for (int r = 0; r < 8; r++) s01[r] = pk2(0.0f, 0.0f);
    #pragma unroll
    for (int d4 = 0; d4 < 32; d4 += 4) {
        float4 kv0 = *(const float4*)&KS(lane, d4);
        float4 kv1 = *(const float4*)&KS(lane + 32, d4);
        u64t kx = pk2(kv0.x, kv1.x);
        u64t ky = pk2(kv0.y, kv1.y);
        u64t kz = pk2(kv0.z, kv1.z);
        u64t kw = pk2(kv0.w, kv1.w);
        #pragma unroll
        for (int r = 0; r < 8; r++) {
            float4 qv = *(const float4*)&QS(wid*8 + r, d4);
            fma2(s01[r], pk2(qv.x, qv.x), kx);
            fma2(s01[r], pk2(qv.y, qv.y), ky);
            fma2(s01[r], pk2(qv.z, qv.z), kz);
            fma2(s01[r], pk2(qv.w, qv.w), kw);
        }
    }
    __syncthreads();

    const float scale = g_scale[h];
    const float kn0 = kn[lane], kn1 = kn[lane + 32];
    const float* rb = g_rel_bias + h * (NTOK * NTOK);
    const float* mk = mask + (size_t)w * (NTOK * NTOK);

    const int swz0 = (lane & 7) << 3;
    const int swz1 = ((lane + 32) & 7) << 3;
    #pragma unroll
    for (int r = 0; r < 8; r++) {
        int n = wid*8 + r;
        float qsc = qn[n] * scale;
        int off = n*64 + lane;
        float2 sv = upk2(s01[r]);
        float x0 = sv.x*qsc*kn0 + rb[off]      + mk[off];
        float x1 = sv.y*qsc*kn1 + rb[off + 32] + mk[off + 32];
        float mx = fmaxf(x0, x1);
        #pragma unroll
        for (int o = 16; o > 0; o >>= 1)
            mx = fmaxf(mx, __shfl_xor_sync(0xffffffffu, mx, o));
        float e0 = __expf(x0 - mx);
        float e1 = __expf(x1 - mx);
        float sm = e0 + e1;
        #pragma unroll
        for (int o = 16; o > 0; o >>= 1)
            sm += __shfl_xor_sync(0xffffffffu, sm, o);
        float inv = 1.0f / sm;
        PT(lane,      n ^ swz0) = e0 * inv;
        PT(lane + 32, n ^ swz1) = e1 * inv;
    }
    __syncthreads();

    u64t o01 = pk2(0.f,0.f), o23 = pk2(0.f,0.f), o45 = pk2(0.f,0.f), o67 = pk2(0.f,0.f);
    #pragma unroll
    for (int m = 0; m < 64; m++) {
        float vm = vs[m][lane];
        u64t vmd = pk2(vm, vm);
        const float* prow = &PT(m, (wid ^ (m & 7)) * 8);
        float4 p0 = *(const float4*)(prow);
        float4 p1 = *(const float4*)(prow + 4);
        fma2(o01, pk2(p0.x, p0.y), vmd);
        fma2(o23, pk2(p0.z, p0.w), vmd);
        fma2(o45, pk2(p1.x, p1.y), vmd);
        fma2(o67, pk2(p1.z, p1.w), vmd);
    }
    float o[8];
    { float2 t = upk2(o01); o[0] = t.x; o[1] = t.y; }
    { float2 t = upk2(o23); o[2] = t.x; o[3] = t.y; }
    { float2 t = upk2(o45); o[4] = t.x; o[5] = t.y; }
    { float2 t = upk2(o67); o[6] = t.x; o[7] = t.y; }

    #pragma unroll
    for (int r = 0; r < 8; r++) {
        size_t oi = (size_t)(b*NTOK + wid*8 + r) * DIM + h*HDIM + lane;
        __nv_bfloat16 hi = __float2bfloat16(o[r]);
        __nv_bfloat16 lo = __float2bfloat16(o[r] - __bfloat162float(hi));
        aoh[oi] = hi;
        aol[oi] = lo;
    }
    #undef QS
    #undef KS
    #undef PT
}

// ---------------------------------------------------------------------------
// Launch order puts gemm_bf16_128<0> at position #4 (the slot ncu profiles).
// Deps: gemm_qkv needs split_x + split_w only; attn needs gemm + cpb_expand.
// ---------------------------------------------------------------------------
extern "C" void kernel_launch(void* const* d_in, const int* in_sizes, int n_in,
                              void* d_out, int out_size)
{
    const float* x           = (const float*)d_in[0];
    const float* mask        = (const float*)d_in[1];
    const float* qkv_w       = (const float*)d_in[2];
    const float* q_bias      = (const float*)d_in[3];
    const float* v_bias      = (const float*)d_in[4];
    const float* logit_scale = (const float*)d_in[5];
    const float* cpb_w1      = (const float*)d_in[6];
    const float* cpb_b1      = (const float*)d_in[7];
    const float* cpb_w2      = (const float*)d_in[8];
    const float* proj_w      = (const float*)d_in[9];
    const float* proj_b      = (const float*)d_in[10];
    const float* rel_table   = (const float*)d_in[11];
    const int*   rel_idx     = (const int*)d_in[12];
    float*       out         = (float*)d_out;

    float *qkv_ptr;
    __nv_bfloat16 *xh, *xl, *wh, *wl, *ph, *pl, *aoh, *aol;
    cudaGetSymbolAddress((void**)&qkv_ptr, g_qkv);
    cudaGetSymbolAddress((void**)&xh, g_xh);   cudaGetSymbolAddress((void**)&xl, g_xl);
    cudaGetSymbolAddress((void**)&wh, g_wh);   cudaGetSymbolAddress((void**)&wl, g_wl);
    cudaGetSymbolAddress((void**)&ph, g_ph);   cudaGetSymbolAddress((void**)&pl, g_pl);
    cudaGetSymbolAddress((void**)&aoh, g_aoh); cudaGetSymbolAddress((void**)&aol, g_aol);

    cudaFuncSetAttribute(gemm_bf16_128<0>, cudaFuncAttributeMaxDynamicSharedMemorySize, GEMM_SMEM);
    cudaFuncSetAttribute(gemm_bf16_128<1>, cudaFuncAttributeMaxDynamicSharedMemorySize, GEMM_SMEM);

    // 1-2: splits feeding the QKV GEMM
    split_f32<<<(ROWS*DIM/4 + 255)/256, 256>>>(x, xh, xl, ROWS*DIM/4);
    split_f32<<<(QKVCOLS*DIM/4 + 255)/256, 256>>>(qkv_w, wh, wl, QKVCOLS*DIM/4);
    // 3: proj weight split
    split_f32<<<(DIM*DIM/4 + 255)/256, 256>>>(proj_w, ph, pl, DIM*DIM/4);

    // 4: QKV GEMM  <-- profiled slot
    gemm_bf16_128<0><<<dim3(QKVCOLS/128, ROWS/128), 512, GEMM_SMEM>>>(
        xh, xl, wh, wl, q_bias, v_bias, qkv_ptr, QKVCOLS);

    // 5-6: CPB
    cpb_mlp_kernel<<<225, 512>>>(rel_table, cpb_w1, cpb_b1, cpb_w2);
    cpb_expand_kernel<<<256, 256>>>(rel_idx, logit_scale);

    // 7: attention
    attn_kernel<<<dim3(BATCH, HEADS), 256>>>(qkv_ptr, mask, aoh, aol);

    // 8: proj GEMM
    gemm_bf16_128<1><<<dim3(DIM/128, ROWS/128), 512, GEMM_SMEM>>>(
        aoh, aol, ph, pl, proj_b, nullptr, out, DIM);
}